// round 2
// baseline (speedup 1.0000x reference)
#include <cuda_runtime.h>
#include <math.h>

namespace {

constexpr int T = 384;
constexpr int SLOTS = 12;   // 32 lanes * 12 = 384 steps

__global__ void __launch_bounds__(32) flif_kernel(
    const float* __restrict__ I,     // [S, T]
    const float* __restrict__ W,     // [4999]
    float* __restrict__ out_spk,     // [S, T]
    float* __restrict__ out_trc)     // [S, T]
{
    __shared__ float wrx[512];       // wr[a] at a + (a>>2) (bank-conflict-free)

    const int lane = threadIdx.x;
    const int s = blockIdx.x;

    #pragma unroll
    for (int it = 0; it < 12; ++it) {
        int a = lane + 32 * it;
        if (a < 384) {
            float v = (a == 0) ? 0.0f : W[4999 - a];  // wr[0]=0 sink, wr[a]=weights[4999-a]
            wrx[a + (a >> 2)] = v;
        }
    }
    __syncwarp();

    const float COEF = (float)(pow(0.1, 0.15) * tgamma(2.0 - 0.15) / 0.5);
    const float DTT  = (float)(0.1 / 20.0);   // DT/TAU

    // This lane's 12 contiguous input samples
    const float4* Ip = reinterpret_cast<const float4*>(I + (size_t)s * T + lane * SLOTS);
    float Ir[SLOTS];
    {
        float4 a = Ip[0], b = Ip[1], c = Ip[2];
        Ir[0]=a.x; Ir[1]=a.y; Ir[2]=a.z;  Ir[3]=a.w;
        Ir[4]=b.x; Ir[5]=b.y; Ir[6]=b.z;  Ir[7]=b.w;
        Ir[8]=c.x; Ir[9]=c.y; Ir[10]=c.z; Ir[11]=c.w;
    }

    float m[SLOTS], d[SLOTS], ot[SLOTS], os[SLOTS];
    #pragma unroll
    for (int r = 0; r < SLOTS; ++r) { m[r]=0.f; d[r]=0.f; ot[r]=0.f; os[r]=0.f; }

    float V = 0.0f;

    #pragma unroll 1
    for (int l0 = 0; l0 < 32; ++l0) {
        const int base12 = SLOTS * (lane - l0);

        // wpos[k] = wr[12*(lane-l0)+k]; clamped negatives hit wr[0]=0
        float wpos[SLOTS];
        #pragma unroll
        for (int k = 1; k < SLOTS; ++k) {
            int idx = base12 + k;
            if (idx < 0) idx = 0;
            wpos[k] = wrx[idx + (idx >> 2)];
        }
        const bool mine = (lane == l0);

        #pragma unroll
        for (int r = 0; r < SLOTS; ++r) {
            // memory for step n = 12*l0 + r lives in lane l0's m[r]
            float mem = __shfl_sync(0xffffffffu, m[r], l0);
            float In  = __shfl_sync(0xffffffffu, Ir[r], l0);

            float spike = (V > -50.0f) ? 1.0f : 0.0f;        // uses PREVIOUS V

            float tt = (-0.025f) * (V + 70.0f) + In;          // -GL*(V-VL) + I
            float Vp = COEF * tt + V - mem;                   // N>=2 branch

            if (l0 == 0) {                                    // uniform first-block specials
                if (r == 1) Vp = V + DTT * (In / 0.025f - V); // N==1
                if (r == 0) Vp = -70.0f;                      // N==0
            }

            float Vnew = Vp - spike * 20.0f;                  // detached reset
            float dr = Vnew - V;
            if (l0 == 0 && r == 0) dr = 0.0f;                 // delta_0 excluded
            d[r] = dr;

            ot[r] = mine ? Vnew  : ot[r];
            os[r] = mine ? spike : os[r];
            V = Vnew;

            // forward scatter: m[r+k] (+= on every lane) gets wr[12*(lane-l0)+k]*dr
            #pragma unroll
            for (int k = 1; k < SLOTS - r; ++k)
                m[r + k] = fmaf(dr, wpos[k], m[r + k]);
        }

        // block-end Toeplitz sweep for offsets dd <= 0 (future lanes only)
        if (l0 < 31) {
            #pragma unroll
            for (int dd = -11; dd <= 0; ++dd) {
                int idx = base12 + dd;
                if (idx < 0) idx = 0;
                float w = wrx[idx + (idx >> 2)];
                #pragma unroll
                for (int c = -dd; c < SLOTS; ++c)
                    m[c + dd] = fmaf(d[c], w, m[c + dd]);
            }
        }
    }

    // coalesced outputs: 12 contiguous floats per lane per array
    size_t base = (size_t)s * T + lane * SLOTS;
    float4* po = reinterpret_cast<float4*>(out_spk + base);
    po[0] = make_float4(os[0], os[1], os[2],  os[3]);
    po[1] = make_float4(os[4], os[5], os[6],  os[7]);
    po[2] = make_float4(os[8], os[9], os[10], os[11]);
    float4* pt = reinterpret_cast<float4*>(out_trc + base);
    pt[0] = make_float4(ot[0], ot[1], ot[2],  ot[3]);
    pt[1] = make_float4(ot[4], ot[5], ot[6],  ot[7]);
    pt[2] = make_float4(ot[8], ot[9], ot[10], ot[11]);
}

} // namespace

extern "C" void kernel_launch(void* const* d_in, const int* in_sizes, int n_in,
                              void* d_out, int out_size) {
    const float* I = (const float*)d_in[0];     // [2048, 384]
    const float* W = (const float*)d_in[1];     // [4999]
    float* out = (float*)d_out;                 // [spk | trc], each 2048*384
    const int S = in_sizes[0] / T;              // 2048
    float* out_spk = out;
    float* out_trc = out + (size_t)S * T;
    flif_kernel<<<S, 32>>>(I, W, out_spk, out_trc);
}

// round 3
// speedup vs baseline: 1.0951x; 1.0951x over previous
#include <cuda_runtime.h>
#include <math.h>

namespace {

constexpr int T = 384;
constexpr int SLOTS = 12;          // 32 lanes * 12 = 384 steps
constexpr int WARPS = 4;           // neurons per CTA
constexpr int NTHREADS = 32 * WARPS;

// Extended, scrambled weight table:
//   logical wr[idx], idx in [-383, 383]; wr[idx<=0] = 0, wr[idx>0] = W[4999-idx]
//   stored at u + (u>>2) where u = idx + 384  (conflict-free for stride-12 lanes)
constexpr int WRX_SIZE = 960;

__global__ void __launch_bounds__(NTHREADS) flif_kernel(
    const float* __restrict__ I,     // [S, T]
    const float* __restrict__ W,     // [4999]
    float* __restrict__ out_spk,     // [S, T]
    float* __restrict__ out_trc)     // [S, T]
{
    __shared__ float wrx[WRX_SIZE];
    __shared__ float sIb[WARPS][T];  // staged I minus GL*VL_abs (= I - 1.75)

    const int tid  = threadIdx.x;
    const int lane = tid & 31;
    const int wid  = tid >> 5;
    const int s    = blockIdx.x * WARPS + wid;

    // Fill extended weight table (768 logical entries, scrambled placement)
    for (int u = tid; u < 768; u += NTHREADS) {
        int idx = u - 384;
        float v = (idx >= 1) ? W[4999 - idx] : 0.0f;
        wrx[u + (u >> 2)] = v;
    }

    // Stage this warp's input, pre-adjusted: Inb = I - GL*(0 - VL) = I - 1.75
    {
        const float4* ip = reinterpret_cast<const float4*>(I + (size_t)s * T);
        float4* sp = reinterpret_cast<float4*>(&sIb[wid][0]);
        #pragma unroll
        for (int q = 0; q < T / 4 / 32; ++q) {           // 3 iterations
            float4 v = ip[lane + 32 * q];
            v.x -= 1.75f; v.y -= 1.75f; v.z -= 1.75f; v.w -= 1.75f;
            sp[lane + 32 * q] = v;
        }
    }
    __syncthreads();

    const float COEF = (float)(pow(0.1, 0.15) * tgamma(2.0 - 0.15) / 0.5);
    const float DTT  = (float)(0.1 / 20.0);   // DT/TAU

    float m[SLOTS], d[SLOTS], ot[SLOTS], os[SLOTS];
    #pragma unroll
    for (int r = 0; r < SLOTS; ++r) { m[r]=0.f; d[r]=0.f; ot[r]=0.f; os[r]=0.f; }

    float V = 0.0f;

    #pragma unroll 1
    for (int l0 = 0; l0 < 32; ++l0) {
        // Per-block scrambled weight base. ubase = 12*(lane-l0)+384 is divisible
        // by 4, so scramble(ubase + j) = sbase + (j + (j>>2)) with j compile-time.
        int ubase = SLOTS * (lane - l0) + 384;
        int sbase = ubase + (ubase >> 2);

        // Forward-scatter weights wr[12*(lane-l0)+k], zero for lanes <= l0 edge cases
        float wpos[SLOTS];
        #pragma unroll
        for (int k = 1; k < SLOTS; ++k)
            wpos[k] = wrx[sbase + (k + (k >> 2))];

        // Block inputs (broadcast LDS.128 x3)
        float Inb[SLOTS];
        {
            const float4* bp = reinterpret_cast<const float4*>(&sIb[wid][SLOTS * l0]);
            float4 a = bp[0], b = bp[1], c = bp[2];
            Inb[0]=a.x; Inb[1]=a.y; Inb[2]=a.z;  Inb[3]=a.w;
            Inb[4]=b.x; Inb[5]=b.y; Inb[6]=b.z;  Inb[7]=b.w;
            Inb[8]=c.x; Inb[9]=c.y; Inb[10]=c.z; Inb[11]=c.w;
        }
        const bool mine = (lane == l0);

        #pragma unroll
        for (int r = 0; r < SLOTS; ++r) {
            // memory term for step n = 12*l0 + r lives in lane l0's m[r]
            float mem = __shfl_sync(0xffffffffu, m[r], l0);

            float spike = (V > -50.0f) ? 1.0f : 0.0f;    // uses PREVIOUS V
            float rst   = spike * 20.0f;

            // Vq = COEF*(-GL*V + (I - 1.75)) + V  (independent of mem: overlaps shfl)
            float Vq = fmaf(COEF, fmaf(-0.025f, V, Inb[r]), V);
            float Vp = Vq - mem;

            if (l0 == 0) {                                // first-block specials
                if (r == 1) {
                    float Inr = Inb[1] + 1.75f;           // raw I
                    Vp = V + DTT * (Inr / 0.025f - V);    // N==1 branch
                }
                if (r == 0) Vp = -70.0f;                  // N==0 branch
            }

            float Vnew = Vp - rst;                        // detached reset
            float dr = Vnew - V;
            if (l0 == 0 && r == 0) dr = 0.0f;             // delta_0 excluded
            d[r] = dr;

            ot[r] = mine ? Vnew  : ot[r];
            os[r] = mine ? spike : os[r];
            V = Vnew;

            // forward scatter: every lane's slot r+k gets wr[12*(lane-l0)+k]*dr
            #pragma unroll
            for (int k = 1; k < SLOTS - r; ++k)
                m[r + k] = fmaf(dr, wpos[k], m[r + k]);
        }

        // block-end Toeplitz sweep, offsets dd in [-11, 0] (serves lanes > l0;
        // lanes <= l0 hit the zero-padded region)
        if (l0 < 31) {
            #pragma unroll
            for (int dd = -11; dd <= 0; ++dd) {
                float w = wrx[sbase + (dd + (dd >> 2))];
                #pragma unroll
                for (int c = -dd; c < SLOTS; ++c)
                    m[c + dd] = fmaf(d[c], w, m[c + dd]);
            }
        }
    }

    // coalesced outputs: 12 contiguous floats per lane per array
    size_t base = (size_t)s * T + lane * SLOTS;
    float4* po = reinterpret_cast<float4*>(out_spk + base);
    po[0] = make_float4(os[0], os[1], os[2],  os[3]);
    po[1] = make_float4(os[4], os[5], os[6],  os[7]);
    po[2] = make_float4(os[8], os[9], os[10], os[11]);
    float4* pt = reinterpret_cast<float4*>(out_trc + base);
    pt[0] = make_float4(ot[0], ot[1], ot[2],  ot[3]);
    pt[1] = make_float4(ot[4], ot[5], ot[6],  ot[7]);
    pt[2] = make_float4(ot[8], ot[9], ot[10], ot[11]);
}

} // namespace

extern "C" void kernel_launch(void* const* d_in, const int* in_sizes, int n_in,
                              void* d_out, int out_size) {
    const float* I = (const float*)d_in[0];     // [2048, 384]
    const float* W = (const float*)d_in[1];     // [4999]
    float* out = (float*)d_out;                 // [spk | trc]
    const int S = in_sizes[0] / T;              // 2048
    float* out_spk = out;
    float* out_trc = out + (size_t)S * T;
    flif_kernel<<<S / WARPS, NTHREADS>>>(I, W, out_spk, out_trc);
}

// round 4
// speedup vs baseline: 1.2464x; 1.1381x over previous
#include <cuda_runtime.h>
#include <math.h>

namespace {

typedef unsigned long long ull;

constexpr int T = 384;
constexpr int SLOTS = 12;     // 32 lanes * 12 = 384 steps

__device__ __forceinline__ ull fma2(ull a, ull b, ull c) {
    ull d; asm("fma.rn.f32x2 %0, %1, %2, %3;" : "=l"(d) : "l"(a), "l"(b), "l"(c));
    return d;
}
__device__ __forceinline__ ull pk(float lo, float hi) {
    ull r; asm("mov.b64 %0, {%1, %2};" : "=l"(r) : "f"(lo), "f"(hi));
    return r;
}
__device__ __forceinline__ float2 upk(ull u) {
    float2 f; asm("mov.b64 {%0, %1}, %2;" : "=f"(f.x), "=f"(f.y) : "l"(u));
    return f;
}

// One warp = 2 neurons (A in .lo, B in .hi of every packed value).
// Lane l owns negated memory accumulators m[0..11] for steps 12l..12l+11.
// Time walks 32 blocks x 12 steps. Per block: seed mloc (current-block memory,
// all lanes) from owner lane's m via shfl; per step the chain is pure FADD/FFMA.
__global__ void __launch_bounds__(32) flif_kernel(
    const float* __restrict__ I,     // [S, T]
    const float* __restrict__ W,     // [4999]
    float* __restrict__ out_spk,     // [S, T]
    float* __restrict__ out_trc)     // [S, T]
{
    // wr[idx], idx in [-383,383]: wr[idx<=0]=0, wr[idx>0]=W[4999-idx].
    // Stored duplicated (w,w) at scrambled slot u+(u>>2), u = idx+384.
    __shared__ float2 wrx[960];
    __shared__ float4 sIb4[T / 2];   // packed inputs (A,B) minus GL*70 = 1.75

    const int lane = threadIdx.x;
    const int gw   = blockIdx.x;
    const int sA   = 2 * gw, sB = 2 * gw + 1;

    for (int u = lane; u < 768; u += 32) {
        int idx = u - 384;
        float v = (idx >= 1) ? W[4999 - idx] : 0.0f;
        wrx[u + (u >> 2)] = make_float2(v, v);
    }
    {
        const float4* ia = reinterpret_cast<const float4*>(I + (size_t)sA * T);
        const float4* ib = reinterpret_cast<const float4*>(I + (size_t)sB * T);
        #pragma unroll
        for (int q = 0; q < 3; ++q) {
            float4 a = ia[lane + 32 * q], b = ib[lane + 32 * q];
            sIb4[(lane + 32 * q) * 2 + 0] =
                make_float4(a.x - 1.75f, b.x - 1.75f, a.y - 1.75f, b.y - 1.75f);
            sIb4[(lane + 32 * q) * 2 + 1] =
                make_float4(a.z - 1.75f, b.z - 1.75f, a.w - 1.75f, b.w - 1.75f);
        }
    }
    __syncthreads();

    const ull* wrxu = reinterpret_cast<const ull*>(wrx);
    const float2* sIb = reinterpret_cast<const float2*>(sIb4);

    const float COEF = (float)(pow(0.1, 0.15) * tgamma(2.0 - 0.15) / 0.5);

    // Block-invariant near-field weights wr[1..11] (packed), for mloc updates.
    ull wnf[SLOTS];
    #pragma unroll
    for (int k = 1; k < SLOTS; ++k) {
        int u = 384 + k;
        wnf[k] = wrxu[u + (u >> 2)];
    }

    ull m[SLOTS], mloc[SLOTS], nd[SLOTS], ot[SLOTS];
    #pragma unroll
    for (int r = 0; r < SLOTS; ++r) { m[r] = 0ull; ot[r] = 0ull; }

    float VA = 0.0f, VB = 0.0f;
    unsigned osA = 0u, osB = 0u;

    #pragma unroll 1
    for (int l0 = 0; l0 < 32; ++l0) {
        const int ubase = SLOTS * (lane - l0) + 384;   // multiple of 4
        const int sbase = ubase + (ubase >> 2);
        const bool mine = (lane == l0);

        // Seed current-block negated memory on ALL lanes from owner lane l0.
        #pragma unroll
        for (int r = 0; r < SLOTS; ++r)
            mloc[r] = __shfl_sync(0xffffffffu, m[r], l0);

        // This lane's forward-scatter weights wr[12*(lane-l0)+k] (0 for past lanes).
        ull w2[SLOTS];
        #pragma unroll
        for (int k = 1; k < SLOTS; ++k)
            w2[k] = wrxu[sbase + (k + (k >> 2))];

        unsigned sba = 0u, sbb = 0u;

        #pragma unroll
        for (int r = 0; r < SLOTS; ++r) {
            float2 In = sIb[SLOTS * l0 + r];           // broadcast LDS.64

            // Spike/reset from PREVIOUS V (off critical chain)
            bool pa = (VA > -50.0f), pb = (VB > -50.0f);
            float rstA = pa ? 20.0f : 0.0f;
            float rstB = pb ? 20.0f : 0.0f;
            sba |= pa ? (1u << r) : 0u;
            sbb |= pb ? (1u << r) : 0u;

            float VqA = fmaf(COEF, fmaf(-0.025f, VA, In.x), VA);
            float VqB = fmaf(COEF, fmaf(-0.025f, VB, In.y), VB);

            float2 ml = upk(mloc[r]);                  // negated memory
            float VpA = VqA + ml.x;
            float VpB = VqB + ml.y;

            if (l0 == 0) {                             // first-block specials
                if (r == 1) {
                    VpA = VA + 0.005f * ((In.x + 1.75f) / 0.025f - VA);
                    VpB = VB + 0.005f * ((In.y + 1.75f) / 0.025f - VB);
                }
                if (r == 0) { VpA = -70.0f; VpB = -70.0f; }
            }

            float VnA = VpA - rstA;                    // detached reset
            float VnB = VpB - rstB;
            float ndA = VA - VnA;                      // NEGATED delta
            float ndB = VB - VnB;
            if (l0 == 0 && r == 0) { ndA = 0.0f; ndB = 0.0f; }

            ull nd2 = pk(ndA, ndB);
            nd[r] = nd2;
            ot[r] = mine ? pk(VnA, VnB) : ot[r];
            VA = VnA; VB = VnB;

            // Scatter into owned future slots + current-block memory (all lanes)
            #pragma unroll
            for (int k = 1; k < SLOTS - r; ++k) {
                m[r + k]    = fma2(nd2, w2[k],  m[r + k]);
                mloc[r + k] = fma2(nd2, wnf[k], mloc[r + k]);
            }
        }

        if (mine) { osA = sba; osB = sbb; }

        // Block-end Toeplitz sweep, offsets dd in [-11,0] (zero weights for past lanes)
        if (l0 < 31) {
            #pragma unroll
            for (int dd = -11; dd <= 0; ++dd) {
                ull w = wrxu[sbase + (dd + (dd >> 2))];
                #pragma unroll
                for (int c = -dd; c < SLOTS; ++c)
                    m[c + dd] = fma2(nd[c], w, m[c + dd]);
            }
        }
    }

    // Outputs: lane holds its 12 steps for both neurons.
    float tA[SLOTS], tB[SLOTS], kA[SLOTS], kB[SLOTS];
    #pragma unroll
    for (int r = 0; r < SLOTS; ++r) {
        float2 v = upk(ot[r]);
        tA[r] = v.x; tB[r] = v.y;
        kA[r] = ((osA >> r) & 1u) ? 1.0f : 0.0f;
        kB[r] = ((osB >> r) & 1u) ? 1.0f : 0.0f;
    }
    const int bo = lane * SLOTS;
    float4* psA = reinterpret_cast<float4*>(out_spk + (size_t)sA * T + bo);
    float4* psB = reinterpret_cast<float4*>(out_spk + (size_t)sB * T + bo);
    float4* ptA = reinterpret_cast<float4*>(out_trc + (size_t)sA * T + bo);
    float4* ptB = reinterpret_cast<float4*>(out_trc + (size_t)sB * T + bo);
    #pragma unroll
    for (int q = 0; q < 3; ++q) {
        psA[q] = make_float4(kA[4*q], kA[4*q+1], kA[4*q+2], kA[4*q+3]);
        psB[q] = make_float4(kB[4*q], kB[4*q+1], kB[4*q+2], kB[4*q+3]);
        ptA[q] = make_float4(tA[4*q], tA[4*q+1], tA[4*q+2], tA[4*q+3]);
        ptB[q] = make_float4(tB[4*q], tB[4*q+1], tB[4*q+2], tB[4*q+3]);
    }
}

} // namespace

extern "C" void kernel_launch(void* const* d_in, const int* in_sizes, int n_in,
                              void* d_out, int out_size) {
    const float* I = (const float*)d_in[0];     // [2048, 384]
    const float* W = (const float*)d_in[1];     // [4999]
    float* out = (float*)d_out;                 // [spk | trc]
    const int S = in_sizes[0] / T;              // 2048
    float* out_spk = out;
    float* out_trc = out + (size_t)S * T;
    flif_kernel<<<S / 2, 32>>>(I, W, out_spk, out_trc);
}

// round 5
// speedup vs baseline: 1.3833x; 1.1099x over previous
#include <cuda_runtime.h>
#include <math.h>

namespace {

typedef unsigned long long ull;

constexpr int T = 384;
constexpr int SLOTS = 12;     // 32 lanes * 12 = 384 steps

__device__ __forceinline__ ull fma2(ull a, ull b, ull c) {
    ull d; asm("fma.rn.f32x2 %0, %1, %2, %3;" : "=l"(d) : "l"(a), "l"(b), "l"(c));
    return d;
}
__device__ __forceinline__ ull add2(ull a, ull b) {
    ull d; asm("add.rn.f32x2 %0, %1, %2;" : "=l"(d) : "l"(a), "l"(b));
    return d;
}
__device__ __forceinline__ ull pk(float lo, float hi) {
    ull r; asm("mov.b64 %0, {%1, %2};" : "=l"(r) : "f"(lo), "f"(hi));
    return r;
}
__device__ __forceinline__ float2 upk(ull u) {
    float2 f; asm("mov.b64 {%0, %1}, %2;" : "=f"(f.x), "=f"(f.y) : "l"(u));
    return f;
}

// One warp = 4 neurons: chain0 = neurons (4g, 4g+1) packed f32x2,
// chain1 = neurons (4g+2, 4g+3). Two independent serial chains give the
// single warp per SMSP enough ILP to cover shfl/FFMA latency.
// Lane l owns NEGATED memory accumulators m[0..11] for steps 12l..12l+11.
__global__ void __launch_bounds__(32) flif_kernel(
    const float* __restrict__ I,     // [S, T]
    const float* __restrict__ W,     // [4999]
    float* __restrict__ out_spk,     // [S, T]
    float* __restrict__ out_trc)     // [S, T]
{
    // wr[idx], idx in [-383,383]: wr[idx<=0]=0, wr[idx>0]=W[4999-idx].
    // Stored duplicated (w,w) at scrambled slot u+(u>>2), u = idx+384.
    __shared__ float2 wrx[960];
    __shared__ ull sI01[T];          // packed (I0,I1) - 1.75
    __shared__ ull sI23[T];          // packed (I2,I3) - 1.75

    const int lane = threadIdx.x;
    const int g    = blockIdx.x;
    const int s0   = 4 * g;

    for (int u = lane; u < 768; u += 32) {
        int idx = u - 384;
        float v = (idx >= 1) ? W[4999 - idx] : 0.0f;
        wrx[u + (u >> 2)] = make_float2(v, v);
    }
    {
        const float* I0 = I + (size_t)(s0 + 0) * T;
        const float* I1 = I + (size_t)(s0 + 1) * T;
        const float* I2 = I + (size_t)(s0 + 2) * T;
        const float* I3 = I + (size_t)(s0 + 3) * T;
        #pragma unroll
        for (int q = 0; q < SLOTS; ++q) {
            int t = lane + 32 * q;                       // coalesced across lanes
            sI01[t] = pk(I0[t] - 1.75f, I1[t] - 1.75f);
            sI23[t] = pk(I2[t] - 1.75f, I3[t] - 1.75f);
        }
    }
    __syncwarp();

    const float COEF = (float)(pow(0.1, 0.15) * tgamma(2.0 - 0.15) / 0.5);
    const ull COEF2 = pk(COEF, COEF);
    const ull MGL2  = pk(-0.025f, -0.025f);
    const ull NEG1  = pk(-1.0f, -1.0f);

    const ull* wrxu = reinterpret_cast<const ull*>(wrx);

    ull m0[SLOTS], m1[SLOTS], nd0[SLOTS], nd1[SLOTS], ot0[SLOTS], ot1[SLOTS];
    #pragma unroll
    for (int r = 0; r < SLOTS; ++r) { m0[r]=0ull; m1[r]=0ull; ot0[r]=0ull; ot1[r]=0ull; }

    ull V0 = 0ull, V1 = 0ull;   // packed V for chain0 / chain1 (init 0.0,0.0)

    #pragma unroll 1
    for (int l0 = 0; l0 < 32; ++l0) {
        const int ubase = SLOTS * (lane - l0) + 384;   // multiple of 4
        const int sbase = ubase + (ubase >> 2);
        const bool mine = (lane == l0);

        // Forward-scatter weights wr[12*(lane-l0)+k] (0 for lanes <= l0 edge)
        ull w2[SLOTS];
        #pragma unroll
        for (int k = 1; k < SLOTS; ++k)
            w2[k] = wrxu[sbase + (k + (k >> 2))];

        #pragma unroll
        for (int r = 0; r < SLOTS; ++r) {
            ull In0 = sI01[SLOTS * l0 + r];            // broadcast LDS.64
            ull In1 = sI23[SLOTS * l0 + r];

            // Memory term for step n=12*l0+r from owner lane l0 (negated)
            ull mem0 = __shfl_sync(0xffffffffu, m0[r], l0);
            ull mem1 = __shfl_sync(0xffffffffu, m1[r], l0);

            float2 v0 = upk(V0), v1 = upk(V1);
            // reset as NEGATIVE value so Vn = Vp + nrst
            ull nrst0 = pk(v0.x > -50.0f ? -20.0f : 0.0f,
                           v0.y > -50.0f ? -20.0f : 0.0f);
            ull nrst1 = pk(v1.x > -50.0f ? -20.0f : 0.0f,
                           v1.y > -50.0f ? -20.0f : 0.0f);

            ull Vq0 = fma2(COEF2, fma2(MGL2, V0, In0), V0);
            ull Vq1 = fma2(COEF2, fma2(MGL2, V1, In1), V1);
            ull Vp0 = add2(Vq0, mem0);                 // + negated memory
            ull Vp1 = add2(Vq1, mem1);

            if (l0 == 0) {                             // first-block specials
                if (r == 0) { Vp0 = pk(-70.0f, -70.0f); Vp1 = pk(-70.0f, -70.0f); }
                if (r == 1) {
                    float2 i0 = upk(In0), i1 = upk(In1);
                    Vp0 = pk(v0.x + 0.005f * ((i0.x + 1.75f) / 0.025f - v0.x),
                             v0.y + 0.005f * ((i0.y + 1.75f) / 0.025f - v0.y));
                    Vp1 = pk(v1.x + 0.005f * ((i1.x + 1.75f) / 0.025f - v1.x),
                             v1.y + 0.005f * ((i1.y + 1.75f) / 0.025f - v1.y));
                }
            }

            ull Vn0 = add2(Vp0, nrst0);                // detached reset
            ull Vn1 = add2(Vp1, nrst1);
            ull d0 = fma2(Vn0, NEG1, V0);              // NEGATED delta = V - Vn
            ull d1 = fma2(Vn1, NEG1, V1);
            if (l0 == 0 && r == 0) { d0 = 0ull; d1 = 0ull; }  // delta_0 excluded

            nd0[r] = d0; nd1[r] = d1;
            ot0[r] = mine ? Vn0 : ot0[r];
            ot1[r] = mine ? Vn1 : ot1[r];
            V0 = Vn0; V1 = Vn1;

            // forward scatter into owned future slots (both chains)
            #pragma unroll
            for (int k = 1; k < SLOTS - r; ++k) {
                m0[r + k] = fma2(d0, w2[k], m0[r + k]);
                m1[r + k] = fma2(d1, w2[k], m1[r + k]);
            }
        }

        // block-end Toeplitz sweep, offsets dd in [-11,0] (zero weights past lanes)
        if (l0 < 31) {
            #pragma unroll
            for (int dd = -11; dd <= 0; ++dd) {
                ull w = wrxu[sbase + (dd + (dd >> 2))];
                #pragma unroll
                for (int c = -dd; c < SLOTS; ++c) {
                    m0[c + dd] = fma2(nd0[c], w, m0[c + dd]);
                    m1[c + dd] = fma2(nd1[c], w, m1[c + dd]);
                }
            }
        }
    }

    // ---- outputs: spikes recomputed from the stored V-trace (exact) ----
    // spike at step n = (V_{n-1} > -50); V before step 12*lane comes from lane-1.
    ull pv0u = __shfl_up_sync(0xffffffffu, ot0[11], 1);
    ull pv1u = __shfl_up_sync(0xffffffffu, ot1[11], 1);
    if (lane == 0) { pv0u = 0ull; pv1u = 0ull; }       // initial V = 0

    float t0a[SLOTS], t0b[SLOTS], t1a[SLOTS], t1b[SLOTS];
    float k0a[SLOTS], k0b[SLOTS], k1a[SLOTS], k1b[SLOTS];
    float2 p0 = upk(pv0u), p1 = upk(pv1u);
    #pragma unroll
    for (int r = 0; r < SLOTS; ++r) {
        float2 c0 = upk(ot0[r]), c1 = upk(ot1[r]);
        t0a[r] = c0.x; t0b[r] = c0.y; t1a[r] = c1.x; t1b[r] = c1.y;
        k0a[r] = (p0.x > -50.0f) ? 1.0f : 0.0f;
        k0b[r] = (p0.y > -50.0f) ? 1.0f : 0.0f;
        k1a[r] = (p1.x > -50.0f) ? 1.0f : 0.0f;
        k1b[r] = (p1.y > -50.0f) ? 1.0f : 0.0f;
        p0 = c0; p1 = c1;
    }

    const int bo = lane * SLOTS;
    #pragma unroll
    for (int q = 0; q < 3; ++q) {
        reinterpret_cast<float4*>(out_spk + (size_t)(s0+0)*T + bo)[q] =
            make_float4(k0a[4*q], k0a[4*q+1], k0a[4*q+2], k0a[4*q+3]);
        reinterpret_cast<float4*>(out_spk + (size_t)(s0+1)*T + bo)[q] =
            make_float4(k0b[4*q], k0b[4*q+1], k0b[4*q+2], k0b[4*q+3]);
        reinterpret_cast<float4*>(out_spk + (size_t)(s0+2)*T + bo)[q] =
            make_float4(k1a[4*q], k1a[4*q+1], k1a[4*q+2], k1a[4*q+3]);
        reinterpret_cast<float4*>(out_spk + (size_t)(s0+3)*T + bo)[q] =
            make_float4(k1b[4*q], k1b[4*q+1], k1b[4*q+2], k1b[4*q+3]);
        reinterpret_cast<float4*>(out_trc + (size_t)(s0+0)*T + bo)[q] =
            make_float4(t0a[4*q], t0a[4*q+1], t0a[4*q+2], t0a[4*q+3]);
        reinterpret_cast<float4*>(out_trc + (size_t)(s0+1)*T + bo)[q] =
            make_float4(t0b[4*q], t0b[4*q+1], t0b[4*q+2], t0b[4*q+3]);
        reinterpret_cast<float4*>(out_trc + (size_t)(s0+2)*T + bo)[q] =
            make_float4(t1a[4*q], t1a[4*q+1], t1a[4*q+2], t1a[4*q+3]);
        reinterpret_cast<float4*>(out_trc + (size_t)(s0+3)*T + bo)[q] =
            make_float4(t1b[4*q], t1b[4*q+1], t1b[4*q+2], t1b[4*q+3]);
    }
}

} // namespace

extern "C" void kernel_launch(void* const* d_in, const int* in_sizes, int n_in,
                              void* d_out, int out_size) {
    const float* I = (const float*)d_in[0];     // [2048, 384]
    const float* W = (const float*)d_in[1];     // [4999]
    float* out = (float*)d_out;                 // [spk | trc]
    const int S = in_sizes[0] / T;              // 2048
    float* out_spk = out;
    float* out_trc = out + (size_t)S * T;
    flif_kernel<<<S / 4, 32>>>(I, W, out_spk, out_trc);
}

// round 6
// speedup vs baseline: 1.4208x; 1.0271x over previous
#include <cuda_runtime.h>
#include <math.h>

namespace {

typedef unsigned long long ull;

constexpr int T = 384;
constexpr int SLOTS = 12;     // 32 lanes * 12 = 384 steps

__device__ __forceinline__ ull fma2(ull a, ull b, ull c) {
    ull d; asm("fma.rn.f32x2 %0, %1, %2, %3;" : "=l"(d) : "l"(a), "l"(b), "l"(c));
    return d;
}
__device__ __forceinline__ ull add2(ull a, ull b) {
    ull d; asm("add.rn.f32x2 %0, %1, %2;" : "=l"(d) : "l"(a), "l"(b));
    return d;
}
__device__ __forceinline__ ull pk(float lo, float hi) {
    ull r; asm("mov.b64 %0, {%1, %2};" : "=l"(r) : "f"(lo), "f"(hi));
    return r;
}
__device__ __forceinline__ float2 upk(ull u) {
    float2 f; asm("mov.b64 {%0, %1}, %2;" : "=f"(f.x), "=f"(f.y) : "l"(u));
    return f;
}

// One warp = 2 neurons (A=.lo, B=.hi of every packed value).
// Lane l owns NEGATED memory accumulators m[0..11] for steps 12l..12l+11.
// Per step: 1 packed shfl for the memory term, 4 packed FMAs for the V update,
// 12 packed FMAs applying the delta to ALL owned slots (weights wr[12D + j - r],
// zero-padded for past lanes -> self-masking; covers near-field AND far-field).
// Owner lane dumps its block's V trace to smem; spikes recomputed at the end.
__global__ void __launch_bounds__(32) flif_kernel(
    const float* __restrict__ I,     // [S, T]
    const float* __restrict__ W,     // [4999]
    float* __restrict__ out_spk,     // [S, T]
    float* __restrict__ out_trc)     // [S, T]
{
    // wr[idx], idx in [-383,383]: wr[idx<=0]=0, wr[idx>0]=W[4999-idx].
    // Stored duplicated (w,w) at scrambled slot u+(u>>2), u = idx+384.
    __shared__ float2 wrx[960];
    __shared__ __align__(16) ull sIn[T];   // COEF*(I-1.75) packed (A,B)
    __shared__ __align__(16) ull strc[T];  // packed V trace

    const int lane = threadIdx.x;
    const int g    = blockIdx.x;
    const int sA   = 2 * g, sB = 2 * g + 1;

    for (int u = lane; u < 768; u += 32) {
        int idx = u - 384;
        float v = (idx >= 1) ? W[4999 - idx] : 0.0f;
        wrx[u + (u >> 2)] = make_float2(v, v);
    }

    const float COEF = (float)(pow(0.1, 0.15) * tgamma(2.0 - 0.15) / 0.5);

    const float* IA = I + (size_t)sA * T;
    const float* IB = I + (size_t)sB * T;
    {
        const float4* ia = reinterpret_cast<const float4*>(IA);
        const float4* ib = reinterpret_cast<const float4*>(IB);
        #pragma unroll
        for (int q = 0; q < 3; ++q) {
            float4 a = ia[lane + 32 * q], b = ib[lane + 32 * q];
            int t = (lane + 32 * q) * 4;
            sIn[t + 0] = pk(COEF * (a.x - 1.75f), COEF * (b.x - 1.75f));
            sIn[t + 1] = pk(COEF * (a.y - 1.75f), COEF * (b.y - 1.75f));
            sIn[t + 2] = pk(COEF * (a.z - 1.75f), COEF * (b.z - 1.75f));
            sIn[t + 3] = pk(COEF * (a.w - 1.75f), COEF * (b.w - 1.75f));
        }
    }
    const float rawA1 = IA[1];   // raw inputs for the exact N==1 branch
    const float rawB1 = IB[1];
    __syncwarp();

    const float af = (float)(1.0 - (double)COEF * 0.025);   // 1 - COEF*GL
    const ull A2   = pk(af, af);
    const ull NEG1 = pk(-1.0f, -1.0f);

    const ull* wrxu = reinterpret_cast<const ull*>(wrx);

    ull m[SLOTS];
    #pragma unroll
    for (int r = 0; r < SLOTS; ++r) m[r] = 0ull;

    ull V = 0ull;         // packed V (init 0,0)
    ull vhold = 0ull;

    #pragma unroll 1
    for (int l0 = 0; l0 < 32; ++l0) {
        const int ubase = SLOTS * (lane - l0) + 384;   // multiple of 4
        const int sbase = ubase + (ubase >> 2);
        const bool mine = (lane == l0);

        // All 23 weights wr[12*(lane-l0) + v], v in [-11,11] (0 for past lanes)
        ull wv[23];
        #pragma unroll
        for (int v = -11; v <= 11; ++v)
            wv[v + 11] = wrxu[sbase + (v + (v >> 2))];

        // Block inputs -> registers (broadcast LDS.128 x6, off-chain)
        ull In[SLOTS];
        {
            const ulonglong2* ip = reinterpret_cast<const ulonglong2*>(&sIn[SLOTS * l0]);
            #pragma unroll
            for (int q = 0; q < 6; ++q) { ulonglong2 p = ip[q]; In[2*q] = p.x; In[2*q+1] = p.y; }
        }

        #pragma unroll
        for (int r = 0; r < SLOTS; ++r) {
            // memory for step n = 12*l0 + r lives in lane l0's m[r] (negated)
            ull mem = __shfl_sync(0xffffffffu, m[r], l0);

            float2 v = upk(V);
            ull nrst = pk(v.x > -50.0f ? -20.0f : 0.0f,
                          v.y > -50.0f ? -20.0f : 0.0f);

            ull Vq = fma2(A2, V, In[r]);          // (1-COEF*GL)*V + COEF*(I-1.75)
            ull Vp = add2(Vq, mem);               // + negated memory

            if (l0 == 0) {                        // first-block specials
                if (r == 0) Vp = pk(-70.0f, -70.0f);
                if (r == 1)
                    Vp = pk(v.x + 0.005f * (rawA1 / 0.025f - v.x),
                            v.y + 0.005f * (rawB1 / 0.025f - v.y));
            }

            ull Vn = add2(Vp, nrst);              // detached reset
            ull nd = fma2(Vn, NEG1, V);           // NEGATED delta = V - Vn
            if (l0 == 0 && r == 0) nd = 0ull;     // delta_0 excluded
            V = Vn;

            // owner captures trace pairwise (STS.128 every 2 steps)
            if (r & 1) {
                if (mine) {
                    ulonglong2 pr; pr.x = vhold; pr.y = Vn;
                    *reinterpret_cast<ulonglong2*>(&strc[SLOTS * l0 + r - 1]) = pr;
                }
            } else vhold = Vn;

            // apply delta to ALL owned slots: weight wr[12D + (j - r)]
            #pragma unroll
            for (int j = 0; j < SLOTS; ++j)
                m[j] = fma2(nd, wv[j - r + 11], m[j]);
        }
    }

    __syncwarp();

    // ---- outputs: spikes from stored trace (spike_n = V_{n-1} > -50), exact ----
    ull pv = (lane == 0) ? 0ull : strc[SLOTS * lane - 1];
    float2 p = upk(pv);
    float tA[SLOTS], tB[SLOTS], kA[SLOTS], kB[SLOTS];
    #pragma unroll
    for (int r = 0; r < SLOTS; ++r) {
        float2 c = upk(strc[SLOTS * lane + r]);
        tA[r] = c.x; tB[r] = c.y;
        kA[r] = (p.x > -50.0f) ? 1.0f : 0.0f;
        kB[r] = (p.y > -50.0f) ? 1.0f : 0.0f;
        p = c;
    }

    const int bo = lane * SLOTS;
    #pragma unroll
    for (int q = 0; q < 3; ++q) {
        reinterpret_cast<float4*>(out_spk + (size_t)sA * T + bo)[q] =
            make_float4(kA[4*q], kA[4*q+1], kA[4*q+2], kA[4*q+3]);
        reinterpret_cast<float4*>(out_spk + (size_t)sB * T + bo)[q] =
            make_float4(kB[4*q], kB[4*q+1], kB[4*q+2], kB[4*q+3]);
        reinterpret_cast<float4*>(out_trc + (size_t)sA * T + bo)[q] =
            make_float4(tA[4*q], tA[4*q+1], tA[4*q+2], tA[4*q+3]);
        reinterpret_cast<float4*>(out_trc + (size_t)sB * T + bo)[q] =
            make_float4(tB[4*q], tB[4*q+1], tB[4*q+2], tB[4*q+3]);
    }
}

} // namespace

extern "C" void kernel_launch(void* const* d_in, const int* in_sizes, int n_in,
                              void* d_out, int out_size) {
    const float* I = (const float*)d_in[0];     // [2048, 384]
    const float* W = (const float*)d_in[1];     // [4999]
    float* out = (float*)d_out;                 // [spk | trc]
    const int S = in_sizes[0] / T;              // 2048
    float* out_spk = out;
    float* out_trc = out + (size_t)S * T;
    flif_kernel<<<S / 2, 32>>>(I, W, out_spk, out_trc);
}